// round 11
// baseline (speedup 1.0000x reference)
#include <cuda_runtime.h>
#include <cuda_fp16.h>
#include <cstdint>
#include <cstddef>

#define L_SEQ  2048
#define NHID_C 512
#define DMODEL 1024
#define BATCH  8

// Scratch (allocation-free), all fp16 except biases
__device__ __half g_qkvh [(size_t)BATCH * 3 * DMODEL * L_SEQ];   // [b][3072][2048]
__device__ __half g_att2h[(size_t)BATCH * L_SEQ * DMODEL];       // [b][2048][1024] (transposed)
__device__ __half g_xth  [(size_t)BATCH * L_SEQ * NHID_C];       // [b][2048][512]
__device__ __half g_wth  [3 * DMODEL * NHID_C];                  // [3072][512]  (q|k|v, m-major,k-contig)
__device__ __half g_woth [NHID_C * DMODEL];                      // [512][1024]
__device__ float  g_bcat [3 * DMODEL];

// ---------------------------------------------------------------------------
// helpers
// ---------------------------------------------------------------------------
__device__ __forceinline__ void ldsm_x4(uint32_t* r, uint32_t addr) {
    asm volatile("ldmatrix.sync.aligned.m8n8.x4.shared.b16 {%0,%1,%2,%3}, [%4];"
        : "=r"(r[0]), "=r"(r[1]), "=r"(r[2]), "=r"(r[3]) : "r"(addr));
}
__device__ __forceinline__ void mma_f16(float* c, const uint32_t* a, uint32_t b0, uint32_t b1) {
    asm volatile("mma.sync.aligned.m16n8k16.row.col.f32.f16.f16.f32 "
        "{%0,%1,%2,%3}, {%4,%5,%6,%7}, {%8,%9}, {%0,%1,%2,%3};"
        : "+f"(c[0]), "+f"(c[1]), "+f"(c[2]), "+f"(c[3])
        : "r"(a[0]), "r"(a[1]), "r"(a[2]), "r"(a[3]), "r"(b0), "r"(b1));
}

// ---------------------------------------------------------------------------
// Pre-pass transposes: fp32 -> fp16, K-major
// ---------------------------------------------------------------------------
__global__ void transpose_x_kernel(const float* __restrict__ x, __half* __restrict__ xt)
{
    __shared__ float tile[32][33];
    int b = blockIdx.z;
    int l0 = blockIdx.x * 32, c0 = blockIdx.y * 32;
    int tx = threadIdx.x, ty = threadIdx.y;
    const float* src = x + (size_t)b * NHID_C * L_SEQ;
    #pragma unroll
    for (int i = 0; i < 32; i += 8)
        tile[ty + i][tx] = src[(size_t)(c0 + ty + i) * L_SEQ + l0 + tx];
    __syncthreads();
    __half* dst = xt + (size_t)b * L_SEQ * NHID_C;
    #pragma unroll
    for (int i = 0; i < 32; i += 8)
        dst[(size_t)(l0 + ty + i) * NHID_C + c0 + tx] = __float2half_rn(tile[tx][ty + i]);
}

// src[R][C] f32 -> dst[C][R] f16
__global__ void transpose_w_kernel(const float* __restrict__ src, __half* __restrict__ dst,
                                   int R, int C)
{
    __shared__ float tile[32][33];
    int c0 = blockIdx.x * 32, r0 = blockIdx.y * 32;
    int tx = threadIdx.x, ty = threadIdx.y;
    #pragma unroll
    for (int i = 0; i < 32; i += 8)
        tile[ty + i][tx] = src[(size_t)(r0 + ty + i) * C + c0 + tx];
    __syncthreads();
    #pragma unroll
    for (int i = 0; i < 32; i += 8)
        dst[(size_t)(c0 + ty + i) * R + r0 + tx] = __float2half_rn(tile[tx][ty + i]);
}

__global__ void bias_cat_kernel(const float* __restrict__ bq, const float* __restrict__ bk,
                                const float* __restrict__ bv, float* __restrict__ dst)
{
    const float* s = (blockIdx.x == 0) ? bq : (blockIdx.x == 1) ? bk : bv;
    dst[blockIdx.x * 1024 + threadIdx.x] = s[threadIdx.x];
}

// ---------------------------------------------------------------------------
// fp16 GEMM: O[b, m, n] = sum_k A[m, k] * X[b, n, k] + bias[m]
//   A [Mtot][Kdim] half (k-contig), X [B][2048][Kdim] half (k-contig)
// CTA 128m x 128n, k-tile 64, 4 warps (warp 64x64), mma m16n8k16,
// ldmatrix + SW128 swizzle, 3-stage cp.async, 2 CTAs/SM.
// ---------------------------------------------------------------------------
#define GSTAGES     3
#define TILE_BYTES  16384            // 128 rows x 128B
#define STAGE_BYTES 32768
#define GEMM_SMEM   (GSTAGES * STAGE_BYTES + 1024)

__global__ void __launch_bounds__(128, 2) gemm_f16_kernel(
    const __half* __restrict__ A,
    const __half* __restrict__ X,
    const float* __restrict__ bias,
    void* __restrict__ Optr,
    int Kdim, int Mtot, int outHalf)
{
    extern __shared__ char smem_raw[];
    const uint32_t sbase =
        ((uint32_t)__cvta_generic_to_shared(smem_raw) + 1023u) & ~1023u;

    const int b  = blockIdx.z;
    const int m0 = blockIdx.y * 128;
    const int n0 = blockIdx.x * 128;
    const int tid  = threadIdx.x;
    const int warp = tid >> 5, lane = tid & 31;
    const int wm = (warp >> 1) * 64;
    const int wn = (warp & 1) * 64;

    const __half* Xb = X + (size_t)b * 2048 * Kdim;

    float acc[4][8][4];
    #pragma unroll
    for (int i = 0; i < 4; i++)
        #pragma unroll
        for (int j = 0; j < 8; j++)
            #pragma unroll
            for (int r = 0; r < 4; r++) acc[i][j][r] = 0.f;

    // copy coords: 16 chunks of 16B per thread per stage (8 A + 8 B)
    // ldmatrix per-thread address components
    const int rowa = wm + (lane & 15);
    const int ktopA = ((lane >> 4) & 1) * 16;              // bytes
    uint32_t aOff[4], aXor[4];
    #pragma unroll
    for (int i = 0; i < 4; i++) {
        int r = rowa + i * 16;
        aOff[i] = (uint32_t)(r * 128);
        aXor[i] = (uint32_t)((r & 7) << 4);
    }
    const int rowb = wn + (lane & 7) + ((lane >> 4) & 1) * 8;
    const int kofsB = ((lane >> 3) & 1) * 16;              // bytes
    uint32_t bOff[4], bXor[4];
    #pragma unroll
    for (int jp = 0; jp < 4; jp++) {
        int r = rowb + jp * 16;
        bOff[jp] = (uint32_t)(r * 128);
        bXor[jp] = (uint32_t)((r & 7) << 4);
    }

    const int T = Kdim >> 6;

    auto issue = [&](int t, int s) {
        const int kt = t << 6;
        uint32_t aB = sbase + (uint32_t)(s * STAGE_BYTES);
        uint32_t bB = aB + TILE_BYTES;
        #pragma unroll
        for (int p = 0; p < 8; p++) {
            int idx = p * 128 + tid;
            int row = idx >> 3, c = idx & 7;
            uint32_t so = (uint32_t)(row * 128) + (uint32_t)((c * 16) ^ ((row & 7) << 4));
            const __half* sA = A + (size_t)(m0 + row) * Kdim + kt + c * 8;
            asm volatile("cp.async.cg.shared.global [%0], [%1], 16;\n"
                         :: "r"(aB + so), "l"(sA));
            const __half* sB = Xb + (size_t)(n0 + row) * Kdim + kt + c * 8;
            asm volatile("cp.async.cg.shared.global [%0], [%1], 16;\n"
                         :: "r"(bB + so), "l"(sB));
        }
    };

    #pragma unroll
    for (int t = 0; t < GSTAGES - 1; t++) {
        if (t < T) issue(t, t);
        asm volatile("cp.async.commit_group;\n");
    }

    int stage = 0;
    for (int t = 0; t < T; t++) {
        asm volatile("cp.async.wait_group %0;\n" :: "n"(GSTAGES - 2));
        __syncthreads();

        int pf = t + GSTAGES - 1;
        if (pf < T) issue(pf, pf % GSTAGES);
        asm volatile("cp.async.commit_group;\n");

        uint32_t stA = sbase + (uint32_t)(stage * STAGE_BYTES);
        uint32_t stB = stA + TILE_BYTES;
        stage = (stage + 1 == GSTAGES) ? 0 : stage + 1;

        #pragma unroll
        for (int kk2 = 0; kk2 < 128; kk2 += 32) {    // k-step of 16 elems = 32B
            uint32_t a[4][4];
            #pragma unroll
            for (int i = 0; i < 4; i++)
                ldsm_x4(a[i], stA + aOff[i] + (((uint32_t)(kk2 + ktopA)) ^ aXor[i]));
            uint32_t bb[4][4];
            #pragma unroll
            for (int jp = 0; jp < 4; jp++)
                ldsm_x4(bb[jp], stB + bOff[jp] + (((uint32_t)(kk2 + kofsB)) ^ bXor[jp]));
            #pragma unroll
            for (int i = 0; i < 4; i++)
                #pragma unroll
                for (int j = 0; j < 8; j++)
                    mma_f16(acc[i][j], a[i], bb[j >> 1][(j & 1) * 2], bb[j >> 1][(j & 1) * 2 + 1]);
        }
    }

    // Epilogue
    const int g  = lane >> 2;
    const int tq = lane & 3;
    __half* Oh = (__half*)Optr + (size_t)b * Mtot * 2048;
    float*  Of = (float*)Optr + (size_t)b * Mtot * 2048;
    #pragma unroll
    for (int i = 0; i < 4; i++) {
        int r0 = m0 + wm + i * 16 + g;
        float bv0 = bias[r0];
        float bv1 = bias[r0 + 8];
        #pragma unroll
        for (int j = 0; j < 8; j++) {
            int col = n0 + wn + j * 8 + tq * 2;
            float v0 = acc[i][j][0] + bv0, v1 = acc[i][j][1] + bv0;
            float v2 = acc[i][j][2] + bv1, v3 = acc[i][j][3] + bv1;
            if (outHalf) {
                *(__half2*)(Oh + (size_t)r0 * 2048 + col)       = __floats2half2_rn(v0, v1);
                *(__half2*)(Oh + (size_t)(r0 + 8) * 2048 + col) = __floats2half2_rn(v2, v3);
            } else {
                *(float2*)(Of + (size_t)r0 * 2048 + col)       = make_float2(v0, v1);
                *(float2*)(Of + (size_t)(r0 + 8) * 2048 + col) = make_float2(v2, v3);
            }
        }
    }
}

// ---------------------------------------------------------------------------
// Attention (fp16 I/O): block = (b, h, 512 l), 256 threads, 2 l per thread.
// Tap math: f = 3c'+w -> channel f&1023, l-offset (f>>10)-1 (warp-uniform).
// Writes transposed att2t[b][l2][c2]: l2 = ((l&31)<<6)+d, c2 = h*64 + (l>>5).
// ---------------------------------------------------------------------------
#define ATT_LD 514     // halves per smem row (conflict-free gather)
#define ATT_SMEM (64 * ATT_LD * 2)

__global__ void __launch_bounds__(256) attn_kernel(__half* __restrict__ att2t)
{
    extern __shared__ __half att_sm[];
    const int b = blockIdx.z, h = blockIdx.y;
    const int l0 = blockIdx.x * 512;
    const int t = threadIdx.x;
    const int l = l0 + 2 * t;
    const int lw = l >> 1;

    const __half2* base2 = (const __half2*)(g_qkvh + (size_t)b * 3 * DMODEL * L_SEQ);
    const __half2* Q2 = base2;
    const __half2* K2 = base2 + (size_t)DMODEL * 1024;
    const __half2* V2 = base2 + (size_t)2 * DMODEL * 1024;
    const int c0 = h * 64;

    float lg[3][2] = {{0.f,0.f},{0.f,0.f},{0.f,0.f}};
    #pragma unroll 4
    for (int d = 0; d < 64; d++) {
        int cp = c0 + d;
        __half2 qh = Q2[cp * 1024 + lw];
        float q0 = __low2float(qh), q1 = __high2float(qh);
        int f = 3 * cp;
        #pragma unroll
        for (int w = 0; w < 3; w++) {
            int ff = f + w, cc = ff & 1023, dl = (ff >> 10) - 1;
            const __half2* Kr = K2 + (size_t)cc * 1024;
            __half2 h0 = Kr[lw];
            float k0, k1;
            if (dl == 0)      { k0 = __low2float(h0); k1 = __high2float(h0); }
            else if (dl < 0)  { k0 = (lw > 0) ? __high2float(Kr[lw - 1]) : 0.f;
                                k1 = __low2float(h0); }
            else              { k0 = __high2float(h0);
                                k1 = (lw < 1023) ? __low2float(Kr[lw + 1]) : 0.f; }
            lg[w][0] += q0 * k0;
            lg[w][1] += q1 * k1;
        }
    }

    float aw[3][2];
    #pragma unroll
    for (int c = 0; c < 2; c++) {
        float m  = fmaxf(lg[0][c], fmaxf(lg[1][c], lg[2][c]));
        float e0 = __expf((lg[0][c] - m) * 0.125f);
        float e1 = __expf((lg[1][c] - m) * 0.125f);
        float e2 = __expf((lg[2][c] - m) * 0.125f);
        float inv = 1.f / (e0 + e1 + e2);
        aw[0][c] = e0 * inv; aw[1][c] = e1 * inv; aw[2][c] = e2 * inv;
    }

    #pragma unroll 4
    for (int d = 0; d < 64; d++) {
        int cp = c0 + d;
        int f = 3 * cp;
        float s0 = 0.f, s1 = 0.f;
        #pragma unroll
        for (int w = 0; w < 3; w++) {
            int ff = f + w, cc = ff & 1023, dl = (ff >> 10) - 1;
            const __half2* Vr = V2 + (size_t)cc * 1024;
            __half2 h0 = Vr[lw];
            float v0, v1;
            if (dl == 0)      { v0 = __low2float(h0); v1 = __high2float(h0); }
            else if (dl < 0)  { v0 = (lw > 0) ? __high2float(Vr[lw - 1]) : 0.f;
                                v1 = __low2float(h0); }
            else              { v0 = __high2float(h0);
                                v1 = (lw < 1023) ? __low2float(Vr[lw + 1]) : 0.f; }
            s0 += aw[w][0] * v0;
            s1 += aw[w][1] * v1;
        }
        *(__half2*)&att_sm[d * ATT_LD + 2 * t] = __floats2half2_rn(s0, s1);
    }
    __syncthreads();

    // gather + transposed store: row l2 gets 16 halves (g=0..15) at c2base
    const int c2base = h * 64 + (l0 >> 5);
    __half* outb = att2t + (size_t)b * L_SEQ * DMODEL;
    #pragma unroll
    for (int it = 0; it < 8; it++) {
        int l2 = it * 256 + t;
        int d = l2 & 63, cl = l2 >> 6;
        unsigned ow[8];
        #pragma unroll
        for (int i = 0; i < 8; i++) {
            __half v0 = att_sm[d * ATT_LD + (2 * i) * 32 + cl];
            __half v1 = att_sm[d * ATT_LD + (2 * i + 1) * 32 + cl];
            __half2 p = __halves2half2(v0, v1);
            ow[i] = *(unsigned*)&p;
        }
        __half* pdst = outb + (size_t)l2 * DMODEL + c2base;
        uint4 u0 = make_uint4(ow[0], ow[1], ow[2], ow[3]);
        uint4 u1 = make_uint4(ow[4], ow[5], ow[6], ow[7]);
        *(uint4*)pdst = u0;
        *((uint4*)pdst + 1) = u1;
    }
}

// ---------------------------------------------------------------------------
extern "C" void kernel_launch(void* const* d_in, const int* in_sizes, int n_in,
                              void* d_out, int out_size)
{
    const float* x  = (const float*)d_in[0];
    const float* wq = (const float*)d_in[1];
    const float* bq = (const float*)d_in[2];
    const float* wk = (const float*)d_in[3];
    const float* bk = (const float*)d_in[4];
    const float* wv = (const float*)d_in[5];
    const float* bv = (const float*)d_in[6];
    const float* wo = (const float*)d_in[7];
    const float* bo = (const float*)d_in[8];
    float* out = (float*)d_out;

    __half* qkvh;  cudaGetSymbolAddress((void**)&qkvh,  g_qkvh);
    __half* att2h; cudaGetSymbolAddress((void**)&att2h, g_att2h);
    __half* xth;   cudaGetSymbolAddress((void**)&xth,   g_xth);
    __half* wth;   cudaGetSymbolAddress((void**)&wth,   g_wth);
    __half* woth;  cudaGetSymbolAddress((void**)&woth,  g_woth);
    float*  bcat;  cudaGetSymbolAddress((void**)&bcat,  g_bcat);

    // Pre-pass: transpose + fp16 convert
    transpose_x_kernel<<<dim3(64, 16, BATCH), dim3(32, 8)>>>(x, xth);
    transpose_w_kernel<<<dim3(32, 16), dim3(32, 8)>>>(wq, wth,                 512, 1024);
    transpose_w_kernel<<<dim3(32, 16), dim3(32, 8)>>>(wk, wth + 1024 * 512,    512, 1024);
    transpose_w_kernel<<<dim3(32, 16), dim3(32, 8)>>>(wv, wth + 2 * 1024 * 512,512, 1024);
    transpose_w_kernel<<<dim3(16, 32), dim3(32, 8)>>>(wo, woth,                1024, 512);
    bias_cat_kernel<<<3, 1024>>>(bq, bk, bv, bcat);

    cudaFuncSetAttribute(gemm_f16_kernel,
                         cudaFuncAttributeMaxDynamicSharedMemorySize, GEMM_SMEM);
    cudaFuncSetAttribute(attn_kernel,
                         cudaFuncAttributeMaxDynamicSharedMemorySize, ATT_SMEM);

    // GEMM1: qkv = wt * xt. M=3072, K=512, N=2048 per batch. half out.
    gemm_f16_kernel<<<dim3(16, 24, BATCH), 128, GEMM_SMEM>>>(
        wth, xth, bcat, qkvh, NHID_C, 3 * DMODEL, 1);

    // Attention: 4 l-tiles x 16 heads x 8 batches, 256 threads.
    attn_kernel<<<dim3(4, 16, BATCH), 256, ATT_SMEM>>>(att2h);

    // GEMM2: out = wot * att2t. M=512, K=1024, N=2048 per batch. float out.
    gemm_f16_kernel<<<dim3(16, 4, BATCH), 128, GEMM_SMEM>>>(
        woth, att2h, bo, out, DMODEL, NHID_C, 0);
}